// round 13
// baseline (speedup 1.0000x reference)
#include <cuda_runtime.h>
#include <cuda_bf16.h>
#include <cstdint>

// ---------------------------------------------------------------------------
// B=8, TGT=256, SRC=512, D=1024, H=16, dh=64, TEMP=0.2
// Output: p_choose (8,16,256,512) then alpha (8,16,256,512), fp32.
// ---------------------------------------------------------------------------

#define D_DIM   1024
#define TGT     256
#define SRC     512
#define NB      8
#define NH      16
#define DH      64
#define BH      (NB*NH)
#define P_ELEMS ((size_t)BH*TGT*SRC)

#define MQ (NB*TGT)     // 2048
#define MK (NB*SRC)     // 4096

// bf16 hi/lo activations (projection outputs; consumed by fused kernel)
__device__ __nv_bfloat16 g_aqh[MQ*D_DIM], g_aql[MQ*D_DIM];
__device__ __nv_bfloat16 g_akh[MK*D_DIM], g_akl[MK*D_DIM];

__device__ __forceinline__ void mma16816(float4& d,
    uint32_t a0, uint32_t a1, uint32_t a2, uint32_t a3,
    uint32_t b0, uint32_t b1)
{
    asm volatile(
        "mma.sync.aligned.m16n8k16.row.col.f32.bf16.bf16.f32 "
        "{%0,%1,%2,%3}, {%4,%5,%6,%7}, {%8,%9}, {%0,%1,%2,%3};"
        : "+f"(d.x), "+f"(d.y), "+f"(d.z), "+f"(d.w)
        : "r"(a0), "r"(a1), "r"(a2), "r"(a3), "r"(b0), "r"(b1));
}

__device__ __forceinline__ void ldm_x4(uint32_t& r0, uint32_t& r1,
                                       uint32_t& r2, uint32_t& r3, uint32_t addr)
{
    asm volatile("ldmatrix.sync.aligned.m8n8.x4.shared.b16 {%0,%1,%2,%3}, [%4];"
                 : "=r"(r0), "=r"(r1), "=r"(r2), "=r"(r3) : "r"(addr));
}

__device__ __forceinline__ void cp_async16(uint32_t smem_dst, const void* gsrc) {
    asm volatile("cp.async.ca.shared.global [%0], [%1], 16;" :: "r"(smem_dst), "l"(gsrc));
}
__device__ __forceinline__ void cp_async_commit() {
    asm volatile("cp.async.commit_group;" ::: "memory");
}
__device__ __forceinline__ void cp_async_wait0() {
    asm volatile("cp.async.wait_group 0;" ::: "memory");
}
__device__ __forceinline__ uint32_t smem_u32(const void* p) {
    uint32_t a;
    asm("{ .reg .u64 t; cvta.to.shared.u64 t, %1; cvt.u32.u64 %0, t; }" : "=r"(a) : "l"(p));
    return a;
}

// split one float4 into hi/lo bf16 quads (same math as the old cvt kernel)
__device__ __forceinline__ void split4(const float4 v, ushort4& h, ushort4& l) {
    __nv_bfloat16 hb, lb;
    hb = __float2bfloat16(v.x); lb = __float2bfloat16(v.x - __bfloat162float(hb));
    h.x = *(unsigned short*)&hb; l.x = *(unsigned short*)&lb;
    hb = __float2bfloat16(v.y); lb = __float2bfloat16(v.y - __bfloat162float(hb));
    h.y = *(unsigned short*)&hb; l.y = *(unsigned short*)&lb;
    hb = __float2bfloat16(v.z); lb = __float2bfloat16(v.z - __bfloat162float(hb));
    h.z = *(unsigned short*)&hb; l.z = *(unsigned short*)&lb;
    hb = __float2bfloat16(v.w); lb = __float2bfloat16(v.w - __bfloat162float(hb));
    h.w = *(unsigned short*)&hb; l.w = *(unsigned short*)&lb;
}

// ---------------------------------------------------------------------------
// mma.sync bf16-split projection GEMM + bias + ReLU -> bf16 hi/lo activations.
// cvt ABSORBED: loader reads original fp32 A/W, splits to hi/lo in registers,
// stores bf16 tiles. Same tile layout/MMA path as before (term-major).
// ---------------------------------------------------------------------------
#define CK      32
#define NCH     (D_DIM/CK)
#define STR     40
#define TILE_BYTES (128*STR*2)
#define BUF_BYTES  (4*TILE_BYTES)
#define PROJ_SMEM  (2*BUF_BYTES)     // 81920; x2 CTAs = 160KB

__global__ __launch_bounds__(256, 2)
void proj_mma(const float* __restrict__ seqs, const float* __restrict__ keys,
              const float* __restrict__ q_w,  const float* __restrict__ q_b,
              const float* __restrict__ k_w,  const float* __restrict__ k_b)
{
    extern __shared__ char smem[];
    const int tid  = threadIdx.x;
    const int wid  = tid >> 5;
    const int lane = tid & 31;
    const int g    = lane >> 2;
    const int t    = lane & 3;
    const int warpM = wid & 3;
    const int warpN = wid >> 2;

    const int by  = blockIdx.y;
    const bool isq = by < 16;
    const int bm  = (isq ? by : by - 16) * 128;
    const int bn  = blockIdx.x * 128;

    const float* Araw = isq ? seqs : keys;
    const float* Wraw = isq ? q_w  : k_w;
    const float* bias = isq ? q_b  : k_b;
    __nv_bfloat16* CH = isq ? g_aqh : g_akh;
    __nv_bfloat16* CL = isq ? g_aql : g_akl;

    float4 acc[2][8];
#pragma unroll
    for (int i = 0; i < 2; i++)
#pragma unroll
        for (int j = 0; j < 8; j++) acc[i][j] = make_float4(0.f, 0.f, 0.f, 0.f);

    const uint32_t smem_base = smem_u32(smem);

    const int aRow    = lane & 15;
    const int aColOff = (lane >> 4) * 8;
    const int wRowOff = (lane & 7) + ((lane >> 4) & 1) * 8;
    const int wColOff = ((lane >> 3) & 1) * 8;

    // loader indices: thread -> (row, 16-col segment)
    const int lrow  = tid >> 1;          // 0..127
    const int lkoff = (tid & 1) * 16;    // 0 or 16

    // load chunk c's fp32 into registers
    auto ldg_chunk = [&](int c, float4 a[4], float4 w[4]) {
        const int k0 = c * CK + lkoff;
        const float* ap = Araw + (size_t)(bm + lrow) * D_DIM + k0;
        const float* wp = Wraw + (size_t)(bn + lrow) * D_DIM + k0;
#pragma unroll
        for (int q = 0; q < 4; q++) {
            a[q] = *(const float4*)(ap + 4 * q);
            w[q] = *(const float4*)(wp + 4 * q);
        }
    };
    // split + store into buffer `buf`
    auto sts_chunk = [&](int buf, const float4 a[4], const float4 w[4]) {
        char* tb = smem + buf * BUF_BYTES;
        uint32_t off = (uint32_t)(lrow * STR + lkoff) * 2;
#pragma unroll
        for (int q = 0; q < 4; q++) {
            ushort4 h, l;
            split4(a[q], h, l);
            *(ushort4*)(tb + off + 8 * q)              = h;   // Ah
            *(ushort4*)(tb + TILE_BYTES + off + 8 * q) = l;   // Al
            split4(w[q], h, l);
            *(ushort4*)(tb + 2*TILE_BYTES + off + 8 * q) = h; // Wh
            *(ushort4*)(tb + 3*TILE_BYTES + off + 8 * q) = l; // Wl
        }
    };

    {
        float4 a[4], w[4];
        ldg_chunk(0, a, w);
        sts_chunk(0, a, w);
    }
    __syncthreads();

    for (int c = 0; c < NCH; c++) {
        const int buf = c & 1;

        float4 na[4], nw[4];
        if (c + 1 < NCH) ldg_chunk(c + 1, na, nw);

        const uint32_t sbAh = smem_base + buf * BUF_BYTES;
        const uint32_t sbAl = sbAh + TILE_BYTES;
        const uint32_t sbWh = sbAh + 2*TILE_BYTES;
        const uint32_t sbWl = sbAh + 3*TILE_BYTES;

        uint32_t aH0 = sbAh + (uint32_t)((warpM*32 +      aRow) * STR + aColOff) * 2;
        uint32_t aH1 = sbAh + (uint32_t)((warpM*32 + 16 + aRow) * STR + aColOff) * 2;
        uint32_t aL0 = sbAl + (uint32_t)((warpM*32 +      aRow) * STR + aColOff) * 2;
        uint32_t aL1 = sbAl + (uint32_t)((warpM*32 + 16 + aRow) * STR + aColOff) * 2;
        uint32_t wH  = sbWh + (uint32_t)((warpN*64 + wRowOff) * STR + wColOff) * 2;
        uint32_t wL  = sbWl + (uint32_t)((warpN*64 + wRowOff) * STR + wColOff) * 2;

#pragma unroll
        for (int ks = 0; ks < CK; ks += 16) {
            const uint32_t kso = (uint32_t)ks * 2;

            uint32_t ah[2][4];
            ldm_x4(ah[0][0], ah[0][1], ah[0][2], ah[0][3], aH0 + kso);
            ldm_x4(ah[1][0], ah[1][1], ah[1][2], ah[1][3], aH1 + kso);
            uint32_t wf[4][4];
#pragma unroll
            for (int q = 0; q < 4; q++)
                ldm_x4(wf[q][0], wf[q][1], wf[q][2], wf[q][3],
                       wH + (uint32_t)(q * 16 * STR) * 2 + kso);

#pragma unroll
            for (int q = 0; q < 4; q++)
#pragma unroll
                for (int i = 0; i < 2; i++) {
                    mma16816(acc[i][2*q],   ah[i][0], ah[i][1], ah[i][2], ah[i][3], wf[q][0], wf[q][1]);
                    mma16816(acc[i][2*q+1], ah[i][0], ah[i][1], ah[i][2], ah[i][3], wf[q][2], wf[q][3]);
                }

            uint32_t al[2][4];
            ldm_x4(al[0][0], al[0][1], al[0][2], al[0][3], aL0 + kso);
            ldm_x4(al[1][0], al[1][1], al[1][2], al[1][3], aL1 + kso);
#pragma unroll
            for (int q = 0; q < 4; q++)
#pragma unroll
                for (int i = 0; i < 2; i++) {
                    mma16816(acc[i][2*q],   al[i][0], al[i][1], al[i][2], al[i][3], wf[q][0], wf[q][1]);
                    mma16816(acc[i][2*q+1], al[i][0], al[i][1], al[i][2], al[i][3], wf[q][2], wf[q][3]);
                }

#pragma unroll
            for (int q = 0; q < 4; q++)
                ldm_x4(wf[q][0], wf[q][1], wf[q][2], wf[q][3],
                       wL + (uint32_t)(q * 16 * STR) * 2 + kso);
#pragma unroll
            for (int q = 0; q < 4; q++)
#pragma unroll
                for (int i = 0; i < 2; i++) {
                    mma16816(acc[i][2*q],   ah[i][0], ah[i][1], ah[i][2], ah[i][3], wf[q][0], wf[q][1]);
                    mma16816(acc[i][2*q+1], ah[i][0], ah[i][1], ah[i][2], ah[i][3], wf[q][2], wf[q][3]);
                }
        }

        if (c + 1 < NCH) sts_chunk(buf ^ 1, na, nw);
        __syncthreads();
    }

#pragma unroll
    for (int i = 0; i < 2; i++) {
        int row0 = bm + warpM * 32 + i * 16 + g;
#pragma unroll
        for (int j = 0; j < 8; j++) {
            int col = bn + warpN * 64 + j * 8 + 2 * t;
            float b0 = bias[col], b1 = bias[col + 1];
            float v[4];
            v[0] = fmaxf(acc[i][j].x + b0, 0.f);
            v[1] = fmaxf(acc[i][j].y + b1, 0.f);
            v[2] = fmaxf(acc[i][j].z + b0, 0.f);
            v[3] = fmaxf(acc[i][j].w + b1, 0.f);
            __nv_bfloat16 h[4], l[4];
#pragma unroll
            for (int u = 0; u < 4; u++) {
                h[u] = __float2bfloat16(v[u]);
                l[u] = __float2bfloat16(v[u] - __bfloat162float(h[u]));
            }
            __nv_bfloat162 h01; h01.x = h[0]; h01.y = h[1];
            __nv_bfloat162 h23; h23.x = h[2]; h23.y = h[3];
            __nv_bfloat162 l01; l01.x = l[0]; l01.y = l[1];
            __nv_bfloat162 l23; l23.x = l[2]; l23.y = l[3];
            *(__nv_bfloat162*)(CH + (size_t)row0 * D_DIM + col)       = h01;
            *(__nv_bfloat162*)(CH + (size_t)(row0 + 8) * D_DIM + col) = h23;
            *(__nv_bfloat162*)(CL + (size_t)row0 * D_DIM + col)       = l01;
            *(__nv_bfloat162*)(CL + (size_t)(row0 + 8) * D_DIM + col) = l23;
        }
    }
}

// ---------------------------------------------------------------------------
// FUSED energy + alpha (unchanged from R12 — known-passing, 77us).
// ---------------------------------------------------------------------------
#define FSTR     72
#define KTILE_B  (SRC*FSTR*2)
#define QTILE_B  (16*FSTR*2)
#define PROW_F   520
#define PBUF_B   (16*PROW_F*4)
#define OFF_KH   0
#define OFF_KL   (OFF_KH + KTILE_B)
#define OFF_Q    (OFF_KL + KTILE_B)
#define OFF_P    (OFF_Q + 4*QTILE_B)
#define FUSED_SMEM (OFF_P + 2*PBUF_B)

__global__ __launch_bounds__(288, 1)
void energy_alpha(const float* __restrict__ ebias,
                  float* __restrict__ P, float* __restrict__ Aout)
{
    extern __shared__ char smem[];
    const int tid  = threadIdx.x;
    const int wid  = tid >> 5;
    const int lane = tid & 31;
    const int g    = lane >> 2;
    const int t    = lane & 3;
    const int bh = blockIdx.x;
    const int bb = bh >> 4;
    const int hh = bh & 15;
    const uint32_t sb = smem_u32(smem);

    const __nv_bfloat16* Qh = g_aqh + (size_t)bb * TGT * D_DIM + hh * DH;
    const __nv_bfloat16* Ql = g_aql + (size_t)bb * TGT * D_DIM + hh * DH;
    const __nv_bfloat16* Kh = g_akh + (size_t)bb * SRC * D_DIM + hh * DH;
    const __nv_bfloat16* Kl = g_akl + (size_t)bb * SRC * D_DIM + hh * DH;

    for (int seg = tid; seg < 4096; seg += 288) {
        int row = seg >> 3, sg = seg & 7;
        uint32_t so = (uint32_t)(row * FSTR + sg * 8) * 2;
        cp_async16(sb + OFF_KH + so, Kh + (size_t)row * D_DIM + sg * 8);
        cp_async16(sb + OFF_KL + so, Kl + (size_t)row * D_DIM + sg * 8);
    }
    if (tid < 256) {
        int tile = tid >> 7, seg = tid & 127;
        int row = seg >> 3, sg = seg & 7;
        uint32_t so = (uint32_t)(row * FSTR + sg * 8) * 2;
        const __nv_bfloat16* src = (tile ? Ql : Qh) + (size_t)row * D_DIM + sg * 8;
        cp_async16(sb + OFF_Q + tile * QTILE_B + so, src);
    }
    cp_async_commit();
    cp_async_wait0();
    __syncthreads();

    const float eb5 = ebias[0] * 5.0f;

    const int aRow    = lane & 15;
    const int aColOff = (lane >> 4) * 8;
    const int wRowOff = (lane & 7) + ((lane >> 4) & 1) * 8;
    const int wColOff = ((lane >> 3) & 1) * 8;

    auto mma_chunk = [&](int X) {
        if (X + 1 < 16) {
            int tile = tid >> 7, seg = tid & 127;
            int row = seg >> 3, sg = seg & 7;
            uint32_t so = (uint32_t)(row * FSTR + sg * 8) * 2;
            const __nv_bfloat16* src = (tile ? Ql : Qh)
                + (size_t)(16 * (X + 1) + row) * D_DIM + sg * 8;
            cp_async16(sb + OFF_Q + (((X + 1) & 1) * 2 + tile) * QTILE_B + so, src);
            cp_async_commit();
            asm volatile("cp.async.wait_group 1;" ::: "memory");
        } else {
            cp_async_wait0();
        }

        const int w = wid;
        const uint32_t qhb = sb + OFF_Q + ((X & 1) * 2 + 0) * QTILE_B
                           + (uint32_t)(aRow * FSTR + aColOff) * 2;
        const uint32_t qlb = sb + OFF_Q + ((X & 1) * 2 + 1) * QTILE_B
                           + (uint32_t)(aRow * FSTR + aColOff) * 2;
        const uint32_t khb = sb + OFF_KH + (uint32_t)((w * 64 + wRowOff) * FSTR + wColOff) * 2;
        const uint32_t klb = sb + OFF_KL + (uint32_t)((w * 64 + wRowOff) * FSTR + wColOff) * 2;

        float4 acc[8];
#pragma unroll
        for (int j = 0; j < 8; j++) acc[j] = make_float4(0.f, 0.f, 0.f, 0.f);

#pragma unroll
        for (int ks = 0; ks < DH; ks += 16) {
            const uint32_t kso = (uint32_t)ks * 2;
            uint32_t ah[4], al[4];
            ldm_x4(ah[0], ah[1], ah[2], ah[3], qhb + kso);
            ldm_x4(al[0], al[1], al[2], al[3], qlb + kso);
            uint32_t wf[4][4];
#pragma unroll
            for (int q = 0; q < 4; q++)
                ldm_x4(wf[q][0], wf[q][1], wf[q][2], wf[q][3],
                       khb + (uint32_t)(q * 16 * FSTR) * 2 + kso);
#pragma unroll
            for (int q = 0; q < 4; q++) {
                mma16816(acc[2*q],   ah[0], ah[1], ah[2], ah[3], wf[q][0], wf[q][1]);
                mma16816(acc[2*q+1], ah[0], ah[1], ah[2], ah[3], wf[q][2], wf[q][3]);
            }
#pragma unroll
            for (int q = 0; q < 4; q++) {
                mma16816(acc[2*q],   al[0], al[1], al[2], al[3], wf[q][0], wf[q][1]);
                mma16816(acc[2*q+1], al[0], al[1], al[2], al[3], wf[q][2], wf[q][3]);
            }
#pragma unroll
            for (int q = 0; q < 4; q++)
                ldm_x4(wf[q][0], wf[q][1], wf[q][2], wf[q][3],
                       klb + (uint32_t)(q * 16 * FSTR) * 2 + kso);
#pragma unroll
            for (int q = 0; q < 4; q++) {
                mma16816(acc[2*q],   ah[0], ah[1], ah[2], ah[3], wf[q][0], wf[q][1]);
                mma16816(acc[2*q+1], ah[0], ah[1], ah[2], ah[3], wf[q][2], wf[q][3]);
            }
        }

        float* pb = (float*)(smem + OFF_P + (X & 1) * PBUF_B);
#pragma unroll
        for (int j = 0; j < 8; j++) {
            int c0 = w * 64 + j * 8 + 2 * t;
            float z0 = fmaf(acc[j].x, 0.625f, eb5);
            float z1 = fmaf(acc[j].y, 0.625f, eb5);
            float z2 = fmaf(acc[j].z, 0.625f, eb5);
            float z3 = fmaf(acc[j].w, 0.625f, eb5);
            float2 pv0, pv1;
            pv0.x = 1.0f / (1.0f + __expf(-z0));
            pv0.y = 1.0f / (1.0f + __expf(-z1));
            pv1.x = 1.0f / (1.0f + __expf(-z2));
            pv1.y = 1.0f / (1.0f + __expf(-z3));
            int f = c0 >> 2;
            int s = f ^ ((f >> 3) & 7);
            int o = c0 & 3;
            *(float2*)(pb + g * PROW_F + s * 4 + o)       = pv0;
            *(float2*)(pb + (g + 8) * PROW_F + s * 4 + o) = pv1;
            float* g0 = P + ((size_t)bh * TGT + 16 * X + g) * SRC + c0;
            *(float2*)g0 = pv0;
            *(float2*)(g0 + (size_t)8 * SRC) = pv1;
        }
    };

    float Bv[16];
#pragma unroll
    for (int j = 0; j < 16; j++) Bv[j] = 0.f;
    if (lane == 0) Bv[0] = 1.f;

    float pc[16], Av[16], PaL[8], PaH[8];
    float k1, k2, k4, k8, k16;

    auto aload = [&](const float* pb, int r, float4 v[4]) {
#pragma unroll
        for (int cc = 0; cc < 4; cc++) {
            int f = 4 * lane + cc;
            int s = f ^ ((f >> 3) & 7);
            v[cc] = *(const float4*)(pb + r * PROW_F + s * 4);
        }
    };

    auto aprep = [&](const float4 v[4]) {
        pc[0]=v[0].x;  pc[1]=v[0].y;  pc[2]=v[0].z;  pc[3]=v[0].w;
        pc[4]=v[1].x;  pc[5]=v[1].y;  pc[6]=v[1].z;  pc[7]=v[1].w;
        pc[8]=v[2].x;  pc[9]=v[2].y;  pc[10]=v[2].z; pc[11]=v[2].w;
        pc[12]=v[3].x; pc[13]=v[3].y; pc[14]=v[3].z; pc[15]=v[3].w;
        float prevlast = __shfl_up_sync(0xffffffffu, pc[15], 1);
        Av[0] = (lane == 0) ? 0.f : (1.f - prevlast);
#pragma unroll
        for (int j = 1; j < 16; j++) Av[j] = 1.f - pc[j-1];
        PaL[0] = Av[0];
#pragma unroll
        for (int j = 1; j < 8; j++) PaL[j] = PaL[j-1] * Av[j];
        PaH[0] = Av[8];
#pragma unroll
        for (int j = 1; j < 8; j++) PaH[j] = PaH[j-1] * Av[8+j];
        float m = PaL[7] * PaH[7], s2;
        k1  = (lane >= 1)  ? m : 0.f;
        s2 = __shfl_up_sync(0xffffffffu, m, 1);  m *= s2;
        k2  = (lane >= 2)  ? m : 0.f;
        s2 = __shfl_up_sync(0xffffffffu, m, 2);  m *= s2;
        k4  = (lane >= 4)  ? m : 0.f;
        s2 = __shfl_up_sync(0xffffffffu, m, 4);  m *= s2;
        k8  = (lane >= 8)  ? m : 0.f;
        s2 = __shfl_up_sync(0xffffffffu, m, 8);  m *= s2;
        k16 = (lane >= 16) ? m : 0.f;
    };

    float4* ar = (float4*)(Aout + (size_t)bh * TGT * SRC + lane * 16);

    if (wid < 8) mma_chunk(0);
    __syncthreads();

    for (int c = 0; c < 16; c++) {
        if (wid < 8) {
            if (c + 1 < 16) mma_chunk(c + 1);
        } else {
            const float* pb = (const float*)(smem + OFF_P + (c & 1) * PBUF_B);
            {
                float4 v0[4];
                aload(pb, 0, v0);
                aprep(v0);
            }
            for (int r = 0; r < 16; r++) {
                float4 nv[4];
                aload(pb, (r < 15) ? (r + 1) : 15, nv);

                float Pl[8], Ph[8];
                Pl[0] = Bv[0];
#pragma unroll
                for (int j = 1; j < 8; j++) Pl[j] = fmaf(Pl[j-1], Av[j], Bv[j]);
                Ph[0] = Bv[8];
#pragma unroll
                for (int j = 1; j < 8; j++) Ph[j] = fmaf(Ph[j-1], Av[8+j], Bv[8+j]);

                float b = fmaf(Pl[7], PaH[7], Ph[7]);
                float s;
                s = __shfl_up_sync(0xffffffffu, b, 1);  b = fmaf(s, k1,  b);
                s = __shfl_up_sync(0xffffffffu, b, 2);  b = fmaf(s, k2,  b);
                s = __shfl_up_sync(0xffffffffu, b, 4);  b = fmaf(s, k4,  b);
                s = __shfl_up_sync(0xffffffffu, b, 8);  b = fmaf(s, k8,  b);
                s = __shfl_up_sync(0xffffffffu, b, 16); b = fmaf(s, k16, b);

                float qin = __shfl_up_sync(0xffffffffu, b, 1);
                qin = (lane == 0) ? 0.f : qin;
                float qmid = fmaf(qin, PaL[7], Pl[7]);

#pragma unroll
                for (int j = 0; j < 8; j++)
                    Bv[j] = pc[j] * fmaf(qin, PaL[j], Pl[j]);
#pragma unroll
                for (int j = 0; j < 8; j++)
                    Bv[8+j] = pc[8+j] * fmaf(qmid, PaH[j], Ph[j]);

                size_t orow = (size_t)(16 * c + r) * 128;
                __stcs(ar + orow + 0, make_float4(Bv[0],  Bv[1],  Bv[2],  Bv[3]));
                __stcs(ar + orow + 1, make_float4(Bv[4],  Bv[5],  Bv[6],  Bv[7]));
                __stcs(ar + orow + 2, make_float4(Bv[8],  Bv[9],  Bv[10], Bv[11]));
                __stcs(ar + orow + 3, make_float4(Bv[12], Bv[13], Bv[14], Bv[15]));

                aprep(nv);
            }
        }
        __syncthreads();
    }
}

// ---------------------------------------------------------------------------
extern "C" void kernel_launch(void* const* d_in, const int* in_sizes, int n_in,
                              void* d_out, int out_size)
{
    const float* seqs  = (const float*)d_in[0];
    const float* keys  = (const float*)d_in[1];
    const float* q_w   = (const float*)d_in[2];
    const float* q_b   = (const float*)d_in[3];
    const float* k_w   = (const float*)d_in[4];
    const float* k_b   = (const float*)d_in[5];
    const float* ebias = (const float*)d_in[6];

    float* p_out = (float*)d_out;
    float* a_out = p_out + P_ELEMS;

    cudaFuncSetAttribute(proj_mma,     cudaFuncAttributeMaxDynamicSharedMemorySize, PROJ_SMEM);
    cudaFuncSetAttribute(energy_alpha, cudaFuncAttributeMaxDynamicSharedMemorySize, FUSED_SMEM);

    proj_mma<<<dim3(8, 48), 256, PROJ_SMEM>>>(seqs, keys, q_w, q_b, k_w, k_b);
    energy_alpha<<<BH, 288, FUSED_SMEM>>>(ebias, p_out, a_out);
}

// round 14
// speedup vs baseline: 1.3168x; 1.3168x over previous
#include <cuda_runtime.h>
#include <cuda_bf16.h>
#include <cstdint>

// ---------------------------------------------------------------------------
// B=8, TGT=256, SRC=512, D=1024, H=16, dh=64, TEMP=0.2
// Output: p_choose (8,16,256,512) then alpha (8,16,256,512), fp32.
// ---------------------------------------------------------------------------

#define D_DIM   1024
#define TGT     256
#define SRC     512
#define NB      8
#define NH      16
#define DH      64
#define BH      (NB*NH)
#define P_ELEMS ((size_t)BH*TGT*SRC)

#define MQ (NB*TGT)     // 2048
#define MK (NB*SRC)     // 4096

// bf16 hi/lo decompositions of inputs
__device__ __nv_bfloat16 g_sh[MQ*D_DIM], g_sl[MQ*D_DIM];
__device__ __nv_bfloat16 g_kh[MK*D_DIM], g_kl[MK*D_DIM];
__device__ __nv_bfloat16 g_qwh[D_DIM*D_DIM], g_qwl[D_DIM*D_DIM];
__device__ __nv_bfloat16 g_kwh[D_DIM*D_DIM], g_kwl[D_DIM*D_DIM];
// bf16 hi/lo activations (projection outputs)
__device__ __nv_bfloat16 g_aqh[MQ*D_DIM], g_aql[MQ*D_DIM];
__device__ __nv_bfloat16 g_akh[MK*D_DIM], g_akl[MK*D_DIM];

__device__ __forceinline__ void mma16816(float4& d,
    uint32_t a0, uint32_t a1, uint32_t a2, uint32_t a3,
    uint32_t b0, uint32_t b1)
{
    asm volatile(
        "mma.sync.aligned.m16n8k16.row.col.f32.bf16.bf16.f32 "
        "{%0,%1,%2,%3}, {%4,%5,%6,%7}, {%8,%9}, {%0,%1,%2,%3};"
        : "+f"(d.x), "+f"(d.y), "+f"(d.z), "+f"(d.w)
        : "r"(a0), "r"(a1), "r"(a2), "r"(a3), "r"(b0), "r"(b1));
}

__device__ __forceinline__ void ldm_x4(uint32_t& r0, uint32_t& r1,
                                       uint32_t& r2, uint32_t& r3, uint32_t addr)
{
    asm volatile("ldmatrix.sync.aligned.m8n8.x4.shared.b16 {%0,%1,%2,%3}, [%4];"
                 : "=r"(r0), "=r"(r1), "=r"(r2), "=r"(r3) : "r"(addr));
}

__device__ __forceinline__ void cp_async16(uint32_t smem_dst, const void* gsrc) {
    asm volatile("cp.async.ca.shared.global [%0], [%1], 16;" :: "r"(smem_dst), "l"(gsrc));
}
__device__ __forceinline__ void cp_async_commit() {
    asm volatile("cp.async.commit_group;" ::: "memory");
}
__device__ __forceinline__ void cp_async_wait0() {
    asm volatile("cp.async.wait_group 0;" ::: "memory");
}
__device__ __forceinline__ uint32_t smem_u32(const void* p) {
    uint32_t a;
    asm("{ .reg .u64 t; cvta.to.shared.u64 t, %1; cvt.u32.u64 %0, t; }" : "=r"(a) : "l"(p));
    return a;
}

// ---------------------------------------------------------------------------
// Fused fp32 -> (hi, lo) bf16 decomposition for all 4 inputs (one launch).
// (reverted to R12 — known 11us)
// ---------------------------------------------------------------------------
#define N4_S  (MQ*D_DIM/4)
#define N4_K  (MK*D_DIM/4)
#define N4_W  (D_DIM*D_DIM/4)
#define CVT_BLOCKS ((N4_S + N4_K + 2*N4_W)/256)

__global__ __launch_bounds__(256)
void cvt_all(const float4* __restrict__ s,  const float4* __restrict__ k,
             const float4* __restrict__ qw, const float4* __restrict__ kw,
             ushort4* __restrict__ sh,  ushort4* __restrict__ sl,
             ushort4* __restrict__ kh,  ushort4* __restrict__ kl,
             ushort4* __restrict__ qwh, ushort4* __restrict__ qwl,
             ushort4* __restrict__ kwh, ushort4* __restrict__ kwl)
{
    int b = blockIdx.x;
    const float4* in; ushort4 *hi, *lo; int idx;
    if (b < N4_S/256) {
        in = s; hi = sh; lo = sl; idx = b * 256 + threadIdx.x;
    } else if (b < (N4_S + N4_K)/256) {
        in = k; hi = kh; lo = kl; idx = (b - N4_S/256) * 256 + threadIdx.x;
    } else if (b < (N4_S + N4_K + N4_W)/256) {
        in = qw; hi = qwh; lo = qwl; idx = (b - (N4_S + N4_K)/256) * 256 + threadIdx.x;
    } else {
        in = kw; hi = kwh; lo = kwl; idx = (b - (N4_S + N4_K + N4_W)/256) * 256 + threadIdx.x;
    }
    float4 v = in[idx];
    ushort4 h, l;
    {
        __nv_bfloat16 hb = __float2bfloat16(v.x);
        __nv_bfloat16 lb = __float2bfloat16(v.x - __bfloat162float(hb));
        h.x = *(unsigned short*)&hb; l.x = *(unsigned short*)&lb;
    }
    {
        __nv_bfloat16 hb = __float2bfloat16(v.y);
        __nv_bfloat16 lb = __float2bfloat16(v.y - __bfloat162float(hb));
        h.y = *(unsigned short*)&hb; l.y = *(unsigned short*)&lb;
    }
    {
        __nv_bfloat16 hb = __float2bfloat16(v.z);
        __nv_bfloat16 lb = __float2bfloat16(v.z - __bfloat162float(hb));
        h.z = *(unsigned short*)&hb; l.z = *(unsigned short*)&lb;
    }
    {
        __nv_bfloat16 hb = __float2bfloat16(v.w);
        __nv_bfloat16 lb = __float2bfloat16(v.w - __bfloat162float(hb));
        h.w = *(unsigned short*)&hb; l.w = *(unsigned short*)&lb;
    }
    hi[idx] = h; lo[idx] = l;
}

// ---------------------------------------------------------------------------
// mma.sync bf16-split projection GEMM + bias + ReLU (reverted to R12 — 124us,
// at the HMMA rt=16 issue floor).
// ---------------------------------------------------------------------------
#define CK      32
#define NCH     (D_DIM/CK)
#define STR     40
#define TILE_BYTES (128*STR*2)
#define BUF_BYTES  (4*TILE_BYTES)
#define PROJ_SMEM  (2*BUF_BYTES)

__global__ __launch_bounds__(256, 2)
void proj_mma(const float* __restrict__ q_b, const float* __restrict__ k_b)
{
    extern __shared__ char smem[];
    const int tid  = threadIdx.x;
    const int wid  = tid >> 5;
    const int lane = tid & 31;
    const int g    = lane >> 2;
    const int t    = lane & 3;
    const int warpM = wid & 3;
    const int warpN = wid >> 2;

    const int by  = blockIdx.y;
    const bool isq = by < 16;
    const int bm  = (isq ? by : by - 16) * 128;
    const int bn  = blockIdx.x * 128;

    const __nv_bfloat16* Ah = isq ? g_sh  : g_kh;
    const __nv_bfloat16* Al = isq ? g_sl  : g_kl;
    const __nv_bfloat16* Wh = isq ? g_qwh : g_kwh;
    const __nv_bfloat16* Wl = isq ? g_qwl : g_kwl;
    const float*       bias = isq ? q_b   : k_b;
    __nv_bfloat16*       CH = isq ? g_aqh : g_akh;
    __nv_bfloat16*       CL = isq ? g_aql : g_akl;

    float4 acc[2][8];
#pragma unroll
    for (int i = 0; i < 2; i++)
#pragma unroll
        for (int j = 0; j < 8; j++) acc[i][j] = make_float4(0.f, 0.f, 0.f, 0.f);

    const uint32_t smem_base = smem_u32(smem);

    const int aRow    = lane & 15;
    const int aColOff = (lane >> 4) * 8;
    const int wRowOff = (lane & 7) + ((lane >> 4) & 1) * 8;
    const int wColOff = ((lane >> 3) & 1) * 8;

    auto load_chunk = [&](int c, int buf) {
        const int k0 = c * CK;
        const uint32_t sb = smem_base + buf * BUF_BYTES;
#pragma unroll
        for (int h = 0; h < 2; h++) {
            int seg = tid + h * 256;
            int row = seg >> 2;
            int s4  = seg & 3;
            uint32_t soff = (uint32_t)(row * STR + s4 * 8) * 2;
            size_t ga = (size_t)(bm + row) * D_DIM + k0 + s4 * 8;
            size_t gw = (size_t)(bn + row) * D_DIM + k0 + s4 * 8;
            cp_async16(sb + soff,                Ah + ga);
            cp_async16(sb + TILE_BYTES   + soff, Al + ga);
            cp_async16(sb + 2*TILE_BYTES + soff, Wh + gw);
            cp_async16(sb + 3*TILE_BYTES + soff, Wl + gw);
        }
        cp_async_commit();
    };

    load_chunk(0, 0);
    cp_async_wait0();
    __syncthreads();

    for (int c = 0; c < NCH; c++) {
        const int buf = c & 1;
        if (c + 1 < NCH) load_chunk(c + 1, buf ^ 1);

        const uint32_t sbAh = smem_base + buf * BUF_BYTES;
        const uint32_t sbAl = sbAh + TILE_BYTES;
        const uint32_t sbWh = sbAh + 2*TILE_BYTES;
        const uint32_t sbWl = sbAh + 3*TILE_BYTES;

        uint32_t aH0 = sbAh + (uint32_t)((warpM*32 +      aRow) * STR + aColOff) * 2;
        uint32_t aH1 = sbAh + (uint32_t)((warpM*32 + 16 + aRow) * STR + aColOff) * 2;
        uint32_t aL0 = sbAl + (uint32_t)((warpM*32 +      aRow) * STR + aColOff) * 2;
        uint32_t aL1 = sbAl + (uint32_t)((warpM*32 + 16 + aRow) * STR + aColOff) * 2;
        uint32_t wH  = sbWh + (uint32_t)((warpN*64 + wRowOff) * STR + wColOff) * 2;
        uint32_t wL  = sbWl + (uint32_t)((warpN*64 + wRowOff) * STR + wColOff) * 2;

#pragma unroll
        for (int ks = 0; ks < CK; ks += 16) {
            const uint32_t kso = (uint32_t)ks * 2;

            uint32_t ah[2][4];
            ldm_x4(ah[0][0], ah[0][1], ah[0][2], ah[0][3], aH0 + kso);
            ldm_x4(ah[1][0], ah[1][1], ah[1][2], ah[1][3], aH1 + kso);
            uint32_t wf[4][4];
#pragma unroll
            for (int q = 0; q < 4; q++)
                ldm_x4(wf[q][0], wf[q][1], wf[q][2], wf[q][3],
                       wH + (uint32_t)(q * 16 * STR) * 2 + kso);

#pragma unroll
            for (int q = 0; q < 4; q++)
#pragma unroll
                for (int i = 0; i < 2; i++) {
                    mma16816(acc[i][2*q],   ah[i][0], ah[i][1], ah[i][2], ah[i][3], wf[q][0], wf[q][1]);
                    mma16816(acc[i][2*q+1], ah[i][0], ah[i][1], ah[i][2], ah[i][3], wf[q][2], wf[q][3]);
                }

            uint32_t al[2][4];
            ldm_x4(al[0][0], al[0][1], al[0][2], al[0][3], aL0 + kso);
            ldm_x4(al[1][0], al[1][1], al[1][2], al[1][3], aL1 + kso);
#pragma unroll
            for (int q = 0; q < 4; q++)
#pragma unroll
                for (int i = 0; i < 2; i++) {
                    mma16816(acc[i][2*q],   al[i][0], al[i][1], al[i][2], al[i][3], wf[q][0], wf[q][1]);
                    mma16816(acc[i][2*q+1], al[i][0], al[i][1], al[i][2], al[i][3], wf[q][2], wf[q][3]);
                }

#pragma unroll
            for (int q = 0; q < 4; q++)
                ldm_x4(wf[q][0], wf[q][1], wf[q][2], wf[q][3],
                       wL + (uint32_t)(q * 16 * STR) * 2 + kso);
#pragma unroll
            for (int q = 0; q < 4; q++)
#pragma unroll
                for (int i = 0; i < 2; i++) {
                    mma16816(acc[i][2*q],   ah[i][0], ah[i][1], ah[i][2], ah[i][3], wf[q][0], wf[q][1]);
                    mma16816(acc[i][2*q+1], ah[i][0], ah[i][1], ah[i][2], ah[i][3], wf[q][2], wf[q][3]);
                }
        }

        cp_async_wait0();
        __syncthreads();
    }

#pragma unroll
    for (int i = 0; i < 2; i++) {
        int row0 = bm + warpM * 32 + i * 16 + g;
#pragma unroll
        for (int j = 0; j < 8; j++) {
            int col = bn + warpN * 64 + j * 8 + 2 * t;
            float b0 = bias[col], b1 = bias[col + 1];
            float v[4];
            v[0] = fmaxf(acc[i][j].x + b0, 0.f);
            v[1] = fmaxf(acc[i][j].y + b1, 0.f);
            v[2] = fmaxf(acc[i][j].z + b0, 0.f);
            v[3] = fmaxf(acc[i][j].w + b1, 0.f);
            __nv_bfloat16 h[4], l[4];
#pragma unroll
            for (int u = 0; u < 4; u++) {
                h[u] = __float2bfloat16(v[u]);
                l[u] = __float2bfloat16(v[u] - __bfloat162float(h[u]));
            }
            __nv_bfloat162 h01; h01.x = h[0]; h01.y = h[1];
            __nv_bfloat162 h23; h23.x = h[2]; h23.y = h[3];
            __nv_bfloat162 l01; l01.x = l[0]; l01.y = l[1];
            __nv_bfloat162 l23; l23.x = l[2]; l23.y = l[3];
            *(__nv_bfloat162*)(CH + (size_t)row0 * D_DIM + col)       = h01;
            *(__nv_bfloat162*)(CH + (size_t)(row0 + 8) * D_DIM + col) = h23;
            *(__nv_bfloat162*)(CL + (size_t)row0 * D_DIM + col)       = l01;
            *(__nv_bfloat162*)(CL + (size_t)(row0 + 8) * D_DIM + col) = l23;
        }
    }
}

// ---------------------------------------------------------------------------
// FUSED energy + alpha, 384 threads / 12 warps.
// Alpha = warp 3 -> SMSP 3, which it owns exclusively (warps 7,10,11 exit
// after the prologue). MMA warps = {0,1,2,4,5,6,8,9} (compact id w = 0..7).
// ---------------------------------------------------------------------------
#define FSTR     72
#define KTILE_B  (SRC*FSTR*2)
#define QTILE_B  (16*FSTR*2)
#define PROW_F   520
#define PBUF_B   (16*PROW_F*4)
#define OFF_KH   0
#define OFF_KL   (OFF_KH + KTILE_B)
#define OFF_Q    (OFF_KL + KTILE_B)
#define OFF_P    (OFF_Q + 4*QTILE_B)
#define FUSED_SMEM (OFF_P + 2*PBUF_B)

__global__ __launch_bounds__(384, 1)
void energy_alpha(const float* __restrict__ ebias,
                  float* __restrict__ P, float* __restrict__ Aout)
{
    extern __shared__ char smem[];
    const int tid  = threadIdx.x;
    const int wid  = tid >> 5;
    const int lane = tid & 31;
    const int g    = lane >> 2;
    const int t    = lane & 3;
    const int bh = blockIdx.x;
    const int bb = bh >> 4;
    const int hh = bh & 15;
    const uint32_t sb = smem_u32(smem);

    const __nv_bfloat16* Qh = g_aqh + (size_t)bb * TGT * D_DIM + hh * DH;
    const __nv_bfloat16* Ql = g_aql + (size_t)bb * TGT * D_DIM + hh * DH;
    const __nv_bfloat16* Kh = g_akh + (size_t)bb * SRC * D_DIM + hh * DH;
    const __nv_bfloat16* Kl = g_akl + (size_t)bb * SRC * D_DIM + hh * DH;

    // ---- prologue: all 12 warps load K tiles + Q chunk 0 ----
    for (int seg = tid; seg < 4096; seg += 384) {
        int row = seg >> 3, sg = seg & 7;
        uint32_t so = (uint32_t)(row * FSTR + sg * 8) * 2;
        cp_async16(sb + OFF_KH + so, Kh + (size_t)row * D_DIM + sg * 8);
        cp_async16(sb + OFF_KL + so, Kl + (size_t)row * D_DIM + sg * 8);
    }
    if (tid < 256) {
        int tile = tid >> 7, seg = tid & 127;
        int row = seg >> 3, sg = seg & 7;
        uint32_t so = (uint32_t)(row * FSTR + sg * 8) * 2;
        const __nv_bfloat16* src = (tile ? Ql : Qh) + (size_t)row * D_DIM + sg * 8;
        cp_async16(sb + OFF_Q + tile * QTILE_B + so, src);
    }
    cp_async_commit();
    cp_async_wait0();
    __syncthreads();

    // spare warps leave: SMSP3 now holds ONLY the alpha warp (wid 3)
    if (wid == 7 || wid == 10 || wid == 11) return;

    const float eb5 = ebias[0] * 5.0f;

    // compact MMA warp id: {0,1,2,4,5,6,8,9} -> 0..7
    const int w    = wid - (wid > 3 ? 1 : 0) - (wid > 7 ? 1 : 0);
    const int mtid = w * 32 + lane;     // 0..255 over MMA warps

    const int aRow    = lane & 15;
    const int aColOff = (lane >> 4) * 8;
    const int wRowOff = (lane & 7) + ((lane >> 4) & 1) * 8;
    const int wColOff = ((lane >> 3) & 1) * 8;

    auto mma_chunk = [&](int X) {
        if (X + 1 < 16) {
            int tile = mtid >> 7, seg = mtid & 127;
            int row = seg >> 3, sg = seg & 7;
            uint32_t so = (uint32_t)(row * FSTR + sg * 8) * 2;
            const __nv_bfloat16* src = (tile ? Ql : Qh)
                + (size_t)(16 * (X + 1) + row) * D_DIM + sg * 8;
            cp_async16(sb + OFF_Q + (((X + 1) & 1) * 2 + tile) * QTILE_B + so, src);
            cp_async_commit();
            asm volatile("cp.async.wait_group 1;" ::: "memory");
        } else {
            cp_async_wait0();
        }

        const uint32_t qhb = sb + OFF_Q + ((X & 1) * 2 + 0) * QTILE_B
                           + (uint32_t)(aRow * FSTR + aColOff) * 2;
        const uint32_t qlb = sb + OFF_Q + ((X & 1) * 2 + 1) * QTILE_B
                           + (uint32_t)(aRow * FSTR + aColOff) * 2;
        const uint32_t khb = sb + OFF_KH + (uint32_t)((w * 64 + wRowOff) * FSTR + wColOff) * 2;
        const uint32_t klb = sb + OFF_KL + (uint32_t)((w * 64 + wRowOff) * FSTR + wColOff) * 2;

        float4 acc[8];
#pragma unroll
        for (int j = 0; j < 8; j++) acc[j] = make_float4(0.f, 0.f, 0.f, 0.f);

#pragma unroll
        for (int ks = 0; ks < DH; ks += 16) {
            const uint32_t kso = (uint32_t)ks * 2;
            uint32_t ah[4], al[4];
            ldm_x4(ah[0], ah[1], ah[2], ah[3], qhb + kso);
            ldm_x4(al[0], al[1], al[2], al[3], qlb + kso);
            uint32_t wf[4][4];
#pragma unroll
            for (int q = 0; q < 4; q++)
                ldm_x4(wf[q][0], wf[q][1], wf[q][2], wf[q][3],
                       khb + (uint32_t)(q * 16 * FSTR) * 2 + kso);
#pragma unroll
            for (int q = 0; q < 4; q++) {
                mma16816(acc[2*q],   ah[0], ah[1], ah[2], ah[3], wf[q][0], wf[q][1]);
                mma16816(acc[2*q+1], ah[0], ah[1], ah[2], ah[3], wf[q][2], wf[q][3]);
            }
#pragma unroll
            for (int q = 0; q < 4; q++) {
                mma16816(acc[2*q],   al[0], al[1], al[2], al[3], wf[q][0], wf[q][1]);
                mma16816(acc[2*q+1], al[0], al[1], al[2], al[3], wf[q][2], wf[q][3]);
            }
#pragma unroll
            for (int q = 0; q < 4; q++)
                ldm_x4(wf[q][0], wf[q][1], wf[q][2], wf[q][3],
                       klb + (uint32_t)(q * 16 * FSTR) * 2 + kso);
#pragma unroll
            for (int q = 0; q < 4; q++) {
                mma16816(acc[2*q],   ah[0], ah[1], ah[2], ah[3], wf[q][0], wf[q][1]);
                mma16816(acc[2*q+1], ah[0], ah[1], ah[2], ah[3], wf[q][2], wf[q][3]);
            }
        }

        float* pb = (float*)(smem + OFF_P + (X & 1) * PBUF_B);
#pragma unroll
        for (int j = 0; j < 8; j++) {
            int c0 = w * 64 + j * 8 + 2 * t;
            float z0 = fmaf(acc[j].x, 0.625f, eb5);
            float z1 = fmaf(acc[j].y, 0.625f, eb5);
            float z2 = fmaf(acc[j].z, 0.625f, eb5);
            float z3 = fmaf(acc[j].w, 0.625f, eb5);
            float2 pv0, pv1;
            pv0.x = 1.0f / (1.0f + __expf(-z0));
            pv0.y = 1.0f / (1.0f + __expf(-z1));
            pv1.x = 1.0f / (1.0f + __expf(-z2));
            pv1.y = 1.0f / (1.0f + __expf(-z3));
            int f = c0 >> 2;
            int s = f ^ ((f >> 3) & 7);
            int o = c0 & 3;
            *(float2*)(pb + g * PROW_F + s * 4 + o)       = pv0;
            *(float2*)(pb + (g + 8) * PROW_F + s * 4 + o) = pv1;
            float* g0 = P + ((size_t)bh * TGT + 16 * X + g) * SRC + c0;
            *(float2*)g0 = pv0;
            *(float2*)(g0 + (size_t)8 * SRC) = pv1;
        }
    };

    // ---- alpha state (warp 3) ----
    float Bv[16];
#pragma unroll
    for (int j = 0; j < 16; j++) Bv[j] = 0.f;
    if (lane == 0) Bv[0] = 1.f;

    float pc[16], Av[16], PaL[8], PaH[8];
    float k1, k2, k4, k8, k16;

    auto aload = [&](const float* pb, int r, float4 v[4]) {
#pragma unroll
        for (int cc = 0; cc < 4; cc++) {
            int f = 4 * lane + cc;
            int s = f ^ ((f >> 3) & 7);
            v[cc] = *(const float4*)(pb + r * PROW_F + s * 4);
        }
    };

    auto aprep = [&](const float4 v[4]) {
        pc[0]=v[0].x;  pc[1]=v[0].y;  pc[2]=v[0].z;  pc[3]=v[0].w;
        pc[4]=v[1].x;  pc[5]=v[1].y;  pc[6]=v[1].z;  pc[7]=v[1].w;
        pc[8]=v[2].x;  pc[9]=v[2].y;  pc[10]=v[2].z; pc[11]=v[2].w;
        pc[12]=v[3].x; pc[13]=v[3].y; pc[14]=v[3].z; pc[15]=v[3].w;
        float prevlast = __shfl_up_sync(0xffffffffu, pc[15], 1);
        Av[0] = (lane == 0) ? 0.f : (1.f - prevlast);
#pragma unroll
        for (int j = 1; j < 16; j++) Av[j] = 1.f - pc[j-1];
        PaL[0] = Av[0];
#pragma unroll
        for (int j = 1; j < 8; j++) PaL[j] = PaL[j-1] * Av[j];
        PaH[0] = Av[8];
#pragma unroll
        for (int j = 1; j < 8; j++) PaH[j] = PaH[j-1] * Av[8+j];
        float m = PaL[7] * PaH[7], s2;
        k1  = (lane >= 1)  ? m : 0.f;
        s2 = __shfl_up_sync(0xffffffffu, m, 1);  m *= s2;
        k2  = (lane >= 2)  ? m : 0.f;
        s2 = __shfl_up_sync(0xffffffffu, m, 2);  m *= s2;
        k4  = (lane >= 4)  ? m : 0.f;
        s2 = __shfl_up_sync(0xffffffffu, m, 4);  m *= s2;
        k8  = (lane >= 8)  ? m : 0.f;
        s2 = __shfl_up_sync(0xffffffffu, m, 8);  m *= s2;
        k16 = (lane >= 16) ? m : 0.f;
    };

    float4* ar = (float4*)(Aout + (size_t)bh * TGT * SRC + lane * 16);

    if (wid != 3) mma_chunk(0);
    __syncthreads();

    for (int c = 0; c < 16; c++) {
        if (wid != 3) {
            if (c + 1 < 16) mma_chunk(c + 1);
        } else {
            const float* pb = (const float*)(smem + OFF_P + (c & 1) * PBUF_B);
            {
                float4 v0[4];
                aload(pb, 0, v0);
                aprep(v0);
            }
            for (int r = 0; r < 16; r++) {
                float4 nv[4];
                aload(pb, (r < 15) ? (r + 1) : 15, nv);

                float Pl[8], Ph[8];
                Pl[0] = Bv[0];
#pragma unroll
                for (int j = 1; j < 8; j++) Pl[j] = fmaf(Pl[j-1], Av[j], Bv[j]);
                Ph[0] = Bv[8];
#pragma unroll
                for (int j = 1; j < 8; j++) Ph[j] = fmaf(Ph[j-1], Av[8+j], Bv[8+j]);

                float b = fmaf(Pl[7], PaH[7], Ph[7]);
                float s;
                s = __shfl_up_sync(0xffffffffu, b, 1);  b = fmaf(s, k1,  b);
                s = __shfl_up_sync(0xffffffffu, b, 2);  b = fmaf(s, k2,  b);
                s = __shfl_up_sync(0xffffffffu, b, 4);  b = fmaf(s, k4,  b);
                s = __shfl_up_sync(0xffffffffu, b, 8);  b = fmaf(s, k8,  b);
                s = __shfl_up_sync(0xffffffffu, b, 16); b = fmaf(s, k16, b);

                float qin = __shfl_up_sync(0xffffffffu, b, 1);
                qin = (lane == 0) ? 0.f : qin;
                float qmid = fmaf(qin, PaL[7], Pl[7]);

#pragma unroll
                for (int j = 0; j < 8; j++)
                    Bv[j] = pc[j] * fmaf(qin, PaL[j], Pl[j]);
#pragma unroll
                for (int j = 0; j < 8; j++)
                    Bv[8+j] = pc[8+j] * fmaf(qmid, PaH[j], Ph[j]);

                size_t orow = (size_t)(16 * c + r) * 128;
                __stcs(ar + orow + 0, make_float4(Bv[0],  Bv[1],  Bv[2],  Bv[3]));
                __stcs(ar + orow + 1, make_float4(Bv[4],  Bv[5],  Bv[6],  Bv[7]));
                __stcs(ar + orow + 2, make_float4(Bv[8],  Bv[9],  Bv[10], Bv[11]));
                __stcs(ar + orow + 3, make_float4(Bv[12], Bv[13], Bv[14], Bv[15]));

                aprep(nv);
            }
        }
        __syncthreads();
    }
}

// ---------------------------------------------------------------------------
extern "C" void kernel_launch(void* const* d_in, const int* in_sizes, int n_in,
                              void* d_out, int out_size)
{
    const float* seqs  = (const float*)d_in[0];
    const float* keys  = (const float*)d_in[1];
    const float* q_w   = (const float*)d_in[2];
    const float* q_b   = (const float*)d_in[3];
    const float* k_w   = (const float*)d_in[4];
    const float* k_b   = (const float*)d_in[5];
    const float* ebias = (const float*)d_in[6];

    float* p_out = (float*)d_out;
    float* a_out = p_out + P_ELEMS;

    void *sh, *sl, *kh, *kl, *qwh, *qwl, *kwh, *kwl;
    cudaGetSymbolAddress(&sh,  g_sh);  cudaGetSymbolAddress(&sl,  g_sl);
    cudaGetSymbolAddress(&kh,  g_kh);  cudaGetSymbolAddress(&kl,  g_kl);
    cudaGetSymbolAddress(&qwh, g_qwh); cudaGetSymbolAddress(&qwl, g_qwl);
    cudaGetSymbolAddress(&kwh, g_kwh); cudaGetSymbolAddress(&kwl, g_kwl);

    cudaFuncSetAttribute(proj_mma,     cudaFuncAttributeMaxDynamicSharedMemorySize, PROJ_SMEM);
    cudaFuncSetAttribute(energy_alpha, cudaFuncAttributeMaxDynamicSharedMemorySize, FUSED_SMEM);

    cvt_all<<<CVT_BLOCKS, 256>>>((const float4*)seqs, (const float4*)keys,
                                 (const float4*)q_w, (const float4*)k_w,
                                 (ushort4*)sh, (ushort4*)sl, (ushort4*)kh, (ushort4*)kl,
                                 (ushort4*)qwh, (ushort4*)qwl, (ushort4*)kwh, (ushort4*)kwl);

    proj_mma<<<dim3(8, 48), 256, PROJ_SMEM>>>(q_b, k_b);
    energy_alpha<<<BH, 384, FUSED_SMEM>>>(ebias, p_out, a_out);
}